// round 7
// baseline (speedup 1.0000x reference)
#include <cuda_runtime.h>
#include <cuda_bf16.h>
#include <math.h>
#include <cstdint>

#define NB 4
#define TT 2048
#define DM 512
#define NH 8
#define HD 64
#define SCALE 0.125f

// ---------------- scratch (no allocation allowed) ----------------
__device__ float g_q[NB * NH * TT * HD];
__device__ float g_k[NB * NH * TT * HD];
__device__ float g_v[NB * NH * TT * HD];
__device__ float g_rc[TT * 32];
__device__ float g_rs[TT * 32];
// bf16 hi/lo planes
__device__ __nv_bfloat16 g_xh[8192 * 512], g_xl[8192 * 512];
__device__ __nv_bfloat16 g_wh[1536 * 512], g_wl[1536 * 512];
__device__ __nv_bfloat16 g_owh[512 * 512], g_owl[512 * 512];
__device__ __nv_bfloat16 g_ch[8192 * 512], g_cl[8192 * 512];

// ---------------- helpers ----------------
__device__ __forceinline__ unsigned pack2(float e0, float e1) {
    unsigned r;
    asm("cvt.rn.bf16x2.f32 %0, %1, %2;" : "=r"(r) : "f"(e1), "f"(e0));
    return r;
}
__device__ __forceinline__ void split2(float f0, float f1, unsigned& hi, unsigned& lo) {
    unsigned h = pack2(f0, f1);
    float h0 = __uint_as_float(h << 16);
    float h1 = __uint_as_float(h & 0xFFFF0000u);
    lo = pack2(f0 - h0, f1 - h1);
    hi = h;
}
__device__ __forceinline__ void mmabf(float* c, const unsigned* a, const unsigned* b) {
    asm volatile(
        "mma.sync.aligned.m16n8k16.row.col.f32.bf16.bf16.f32 "
        "{%0,%1,%2,%3},{%4,%5,%6,%7},{%8,%9},{%0,%1,%2,%3};"
        : "+f"(c[0]), "+f"(c[1]), "+f"(c[2]), "+f"(c[3])
        : "r"(a[0]), "r"(a[1]), "r"(a[2]), "r"(a[3]), "r"(b[0]), "r"(b[1]));
}
__device__ __forceinline__ uint32_t smem_u32(const void* p) {
    uint32_t a;
    asm("{ .reg .u64 t; cvta.to.shared.u64 t, %1; cvt.u32.u64 %0, t; }" : "=r"(a) : "l"(p));
    return a;
}
__device__ __forceinline__ void ldsm_x4(unsigned* r, uint32_t addr) {
    asm volatile("ldmatrix.sync.aligned.m8n8.x4.shared.b16 {%0,%1,%2,%3}, [%4];"
                 : "=r"(r[0]), "=r"(r[1]), "=r"(r[2]), "=r"(r[3]) : "r"(addr));
}
__device__ __forceinline__ void cp16(uint32_t saddr, const void* gaddr) {
    asm volatile("cp.async.cg.shared.global [%0], [%1], 16;" :: "r"(saddr), "l"(gaddr));
}
#define CP_COMMIT() asm volatile("cp.async.commit_group;" ::: "memory")
#define CP_WAIT(N) asm volatile("cp.async.wait_group %0;" :: "n"(N) : "memory")

// ---------------------------------------------------------------------------
// fp32 -> bf16 hi/lo planes (one thread per float4)
// ---------------------------------------------------------------------------
__global__ void __launch_bounds__(256) conv_kernel(const float* __restrict__ src,
                                                   __nv_bfloat16* __restrict__ hi,
                                                   __nv_bfloat16* __restrict__ lo, int n4) {
    int i = blockIdx.x * 256 + threadIdx.x;
    if (i >= n4) return;
    float4 v = ((const float4*)src)[i];
    unsigned h0, l0, h1, l1;
    split2(v.x, v.y, h0, l0);
    split2(v.z, v.w, h1, l1);
    ((uint2*)hi)[i] = make_uint2(h0, h1);
    ((uint2*)lo)[i] = make_uint2(l0, l1);
}

// ---------------------------------------------------------------------------
// BF16x3 GEMM, cp.async staging of pre-split planes.
// Block 128m x 128e, 8 warps (2m x 4e), warp tile 64m x 32e.
// K-chunk 32 (2 k16 steps), double-buffered. smem row stride 20 u32 (80B).
// ---------------------------------------------------------------------------
#define GS 20
#define PLN (128 * GS)     // 2560 u32 per plane
#define GBUF (4 * PLN)     // per buffer u32 (40KB)

template <bool QKV>
__global__ void __launch_bounds__(256) gemm_bf(const float* __restrict__ bias,
                                               float* __restrict__ out) {
    extern __shared__ unsigned gsm[];
    const uint32_t sbase = smem_u32(gsm);

    const int e0 = blockIdx.x * 128;
    const int m0 = blockIdx.y * 128;
    const int tid = threadIdx.x;
    const int wid = tid >> 5, lane = tid & 31;
    const int wm = wid >> 2, wn = wid & 3;   // 2m x 4e
    const int g = lane >> 2, t4 = lane & 3;

    const __nv_bfloat16* Ah = QKV ? g_xh : g_ch;
    const __nv_bfloat16* Al = QKV ? g_xl : g_cl;
    const __nv_bfloat16* Bh = QKV ? g_wh : g_owh;
    const __nv_bfloat16* Bl = QKV ? g_wl : g_owl;

    float acc[4][4][4];
#pragma unroll
    for (int mt = 0; mt < 4; mt++)
#pragma unroll
        for (int nt = 0; nt < 4; nt++)
#pragma unroll
            for (int r = 0; r < 4; r++) acc[mt][nt][r] = 0.f;

    // stage chunk kc into buffer b: 2048 16B-cells (4 planes x 128 rows x 4)
    auto stage = [&](int kc, int b) {
#pragma unroll
        for (int i = 0; i < 8; i++) {
            int idx = tid + i * 256;
            int p = idx >> 9;             // 0 Ah, 1 Al, 2 Bh, 3 Bl
            int w = idx & 511;
            int r = w >> 2, cell = w & 3;
            const __nv_bfloat16* srcp = (p == 0) ? Ah : (p == 1) ? Al : (p == 2) ? Bh : Bl;
            int row = (p < 2 ? m0 : e0) + r;
            const void* gp = srcp + (size_t)row * 512 + kc + cell * 8;
            uint32_t sp = sbase + (uint32_t)(b * GBUF + p * PLN + r * GS + cell * 4) * 4;
            cp16(sp, gp);
        }
        CP_COMMIT();
    };

    // ldmatrix lane-address components (bytes, stride 80)
    const uint32_t aRowOff = (uint32_t)(lane & 15) * 80;
    const uint32_t aColOff = (uint32_t)(lane >> 4) * 16;
    const uint32_t bRowOff = (uint32_t)((lane & 7) + ((lane >> 4) << 3)) * 80;
    const uint32_t bColOff = (uint32_t)((lane >> 3) & 1) * 16;

    stage(0, 0);

    for (int c = 0; c < 16; c++) {
        const int b = c & 1;
        if (c < 15) stage(c * 32 + 32, b ^ 1);
        if (c < 15) CP_WAIT(1); else CP_WAIT(0);
        __syncthreads();

        const uint32_t bb = sbase + b * (GBUF * 4);
#pragma unroll
        for (int ks = 0; ks < 2; ks++) {
            const uint32_t kOff = ks * 32;
            unsigned ah[4][4], al[4][4], bh[2][4], bl[2][4];
#pragma unroll
            for (int mt = 0; mt < 4; mt++) {
                uint32_t base = bb + (wm * 64 + mt * 16) * 80 + aRowOff + kOff + aColOff;
                ldsm_x4(ah[mt], base);
                ldsm_x4(al[mt], base + PLN * 4);
            }
#pragma unroll
            for (int ntp = 0; ntp < 2; ntp++) {
                uint32_t base = bb + (wn * 32 + ntp * 16) * 80 + bRowOff + kOff + bColOff +
                                2 * PLN * 4;
                ldsm_x4(bh[ntp], base);
                ldsm_x4(bl[ntp], base + PLN * 4);
            }
#pragma unroll
            for (int mt = 0; mt < 4; mt++)
#pragma unroll
                for (int nt = 0; nt < 4; nt++) {
                    const unsigned* BH = &bh[nt >> 1][(nt & 1) * 2];
                    const unsigned* BL = &bl[nt >> 1][(nt & 1) * 2];
                    mmabf(acc[mt][nt], ah[mt], BH);
                    mmabf(acc[mt][nt], al[mt], BH);
                    mmabf(acc[mt][nt], ah[mt], BL);
                }
        }
        __syncthreads();
    }

    if (QKV) {
#pragma unroll
        for (int mt = 0; mt < 4; mt++)
#pragma unroll
            for (int half = 0; half < 2; half++) {
                int m = m0 + wm * 64 + mt * 16 + g + half * 8;
                int nbt = m >> 11, tt = m & 2047;
#pragma unroll
                for (int nt = 0; nt < 4; nt++) {
                    int e = e0 + wn * 32 + nt * 8 + t4 * 2;
                    int sec = e >> 9;
                    int h = (e >> 6) & 7;
                    int d = e & 63;
                    float* buf = (sec == 0) ? g_q : (sec == 1) ? g_k : g_v;
                    *(float2*)(buf + (((size_t)(nbt * NH + h)) * TT + tt) * HD + d) =
                        make_float2(acc[mt][nt][half * 2], acc[mt][nt][half * 2 + 1]);
                }
            }
    } else {
#pragma unroll
        for (int mt = 0; mt < 4; mt++)
#pragma unroll
            for (int half = 0; half < 2; half++) {
                int m = m0 + wm * 64 + mt * 16 + g + half * 8;
#pragma unroll
                for (int nt = 0; nt < 4; nt++) {
                    int e = e0 + wn * 32 + nt * 8 + t4 * 2;
                    float2 bv = *(const float2*)(bias + e);
                    *(float2*)(out + (size_t)m * 512 + e) =
                        make_float2(acc[mt][nt][half * 2] + bv.x,
                                    acc[mt][nt][half * 2 + 1] + bv.y);
                }
            }
    }
}

// ---------------------------------------------------------------------------
// RoPE trig table (double math once; applied in attention staging)
// ---------------------------------------------------------------------------
__global__ void __launch_bounds__(256) rope_table_kernel() {
    int idx = blockIdx.x * 256 + threadIdx.x;
    if (idx >= TT * 32) return;
    int t = idx >> 5, lane = idx & 31;
    double inv_freq = pow(10000.0, -((double)(2 * lane) / 64.0));
    float ang = (float)t * (float)inv_freq;
    g_rc[idx] = (float)cos((double)ang);
    g_rs[idx] = (float)sin((double)ang);
}

// ---------------------------------------------------------------------------
// Sliding-window attention, bf16x3, ldmatrix, fused RoPE (R6 known-good core);
// epilogue writes ctx as bf16 hi/lo planes.
// ---------------------------------------------------------------------------
#define KHI 0
#define KLO 4608
#define VHI 9216
#define VLO 13568
#define PHI 17920
#define PLO 26624
#define QHI PHI
#define QLO (PHI + 4608)

__global__ void __launch_bounds__(256) attn_kernel() {
    extern __shared__ unsigned sv[];
    const uint32_t sbase = smem_u32(sv);

    const int qt = blockIdx.x;
    const int h = blockIdx.y;
    const int n = blockIdx.z;
    const int q0 = qt * 128;
    const int tid = threadIdx.x;
    const int wid = tid >> 5, lane = tid & 31;
    const int g = lane >> 2, t4 = lane & 3;
    const int qr = wid * 16 + g;

    const size_t hb = ((size_t)(n * NH + h)) * TT * HD;
    const float* qg = g_q + hb;
    const float* kg = g_k + hb;
    const float* vg = g_v + hb;

    const uint32_t aRow36 = (uint32_t)(lane & 15) * 144;
    const uint32_t aRow68 = (uint32_t)(lane & 15) * 272;
    const uint32_t aColH = (uint32_t)(lane >> 4) * 16;
    const uint32_t bRow36 = (uint32_t)((lane & 7) + ((lane >> 4) << 3)) * 144;
    const uint32_t bRow68 = (uint32_t)((lane & 7) + ((lane >> 4) << 3)) * 272;
    const uint32_t bColH = (uint32_t)((lane >> 3) & 1) * 16;

    // stage Q with fused RoPE
#pragma unroll
    for (int i = 0; i < 4; i++) {
        int idx = tid + i * 256;
        int r = idx >> 3, d4 = idx & 7;
        const float* row = qg + (size_t)(q0 + r) * HD;
        float4 a = *(const float4*)(row + d4 * 4);
        float4 b = *(const float4*)(row + d4 * 4 + 32);
        const float4 cv = *(const float4*)(g_rc + (size_t)(q0 + r) * 32 + d4 * 4);
        const float4 sn = *(const float4*)(g_rs + (size_t)(q0 + r) * 32 + d4 * 4);
        float4 lo = make_float4(a.x * cv.x - b.x * sn.x, a.y * cv.y - b.y * sn.y,
                                a.z * cv.z - b.z * sn.z, a.w * cv.w - b.w * sn.w);
        float4 hi = make_float4(b.x * cv.x + a.x * sn.x, b.y * cv.y + a.y * sn.y,
                                b.z * cv.z + a.z * sn.z, b.w * cv.w + a.w * sn.w);
        unsigned h0, l0, h1, l1;
        split2(lo.x, lo.y, h0, l0);
        split2(lo.z, lo.w, h1, l1);
        *(uint2*)&sv[QHI + r * 36 + d4 * 2] = make_uint2(h0, h1);
        *(uint2*)&sv[QLO + r * 36 + d4 * 2] = make_uint2(l0, l1);
        split2(hi.x, hi.y, h0, l0);
        split2(hi.z, hi.w, h1, l1);
        *(uint2*)&sv[QHI + r * 36 + (d4 + 8) * 2] = make_uint2(h0, h1);
        *(uint2*)&sv[QLO + r * 36 + (d4 + 8) * 2] = make_uint2(l0, l1);
    }
    __syncthreads();

    unsigned aqh[4][4], aql[4][4];
#pragma unroll
    for (int ks = 0; ks < 4; ks++) {
        uint32_t base = sbase + (wid * 16) * 144 + aRow36 + ks * 32 + aColH;
        ldsm_x4(aqh[ks], base + QHI * 4);
        ldsm_x4(aql[ks], base + QLO * 4);
    }
    __syncthreads();

    float m_i[2] = {-1e30f, -1e30f};
    float l_i[2] = {0.f, 0.f};
    float o[8][4];
#pragma unroll
    for (int nt = 0; nt < 8; nt++)
#pragma unroll
        for (int r = 0; r < 4; r++) o[nt][r] = 0.f;

    int c0 = qt - 1; if (c0 < 0) c0 = 0;
    int c1 = qt + 1; if (c1 > 15) c1 = 15;

    for (int c = c0; c <= c1; c++) {
        const int j0 = c * 128;

        const int rowlo = q0 + wid * 16;
        int ntLo = (rowlo - 127 - j0) >> 3;
        if (ntLo < 0) ntLo = 0;
        ntLo &= ~1;
        int ntHi = (rowlo + 15 + 128 - j0) >> 3;
        if (ntHi > 15) ntHi = 15;
        ntHi |= 1;
        const int kspLo = ntLo >> 1, kspHi = ntHi >> 1;

        // stage K with fused RoPE
#pragma unroll
        for (int i = 0; i < 4; i++) {
            int idx = tid + i * 256;
            int r = idx >> 3, d4 = idx & 7;
            const float* row = kg + (size_t)(j0 + r) * HD;
            float4 a = *(const float4*)(row + d4 * 4);
            float4 b = *(const float4*)(row + d4 * 4 + 32);
            const float4 cv = *(const float4*)(g_rc + (size_t)(j0 + r) * 32 + d4 * 4);
            const float4 sn = *(const float4*)(g_rs + (size_t)(j0 + r) * 32 + d4 * 4);
            float4 lo = make_float4(a.x * cv.x - b.x * sn.x, a.y * cv.y - b.y * sn.y,
                                    a.z * cv.z - b.z * sn.z, a.w * cv.w - b.w * sn.w);
            float4 hi = make_float4(b.x * cv.x + a.x * sn.x, b.y * cv.y + a.y * sn.y,
                                    b.z * cv.z + a.z * sn.z, b.w * cv.w + a.w * sn.w);
            unsigned h0, l0, h1, l1;
            split2(lo.x, lo.y, h0, l0);
            split2(lo.z, lo.w, h1, l1);
            *(uint2*)&sv[KHI + r * 36 + d4 * 2] = make_uint2(h0, h1);
            *(uint2*)&sv[KLO + r * 36 + d4 * 2] = make_uint2(l0, l1);
            split2(hi.x, hi.y, h0, l0);
            split2(hi.z, hi.w, h1, l1);
            *(uint2*)&sv[KHI + r * 36 + (d4 + 8) * 2] = make_uint2(h0, h1);
            *(uint2*)&sv[KLO + r * 36 + (d4 + 8) * 2] = make_uint2(l0, l1);
        }
        // stage V transposed
#pragma unroll
        for (int i = 0; i < 4; i++) {
            int idx = tid + i * 256;
            int rp = idx >> 4, d4 = idx & 15;
            float4 va = *(const float4*)(vg + (size_t)(j0 + 2 * rp) * HD + d4 * 4);
            float4 vb = *(const float4*)(vg + (size_t)(j0 + 2 * rp + 1) * HD + d4 * 4);
            unsigned hh, ll;
            split2(va.x, vb.x, hh, ll);
            sv[VHI + (d4 * 4 + 0) * 68 + rp] = hh; sv[VLO + (d4 * 4 + 0) * 68 + rp] = ll;
            split2(va.y, vb.y, hh, ll);
            sv[VHI + (d4 * 4 + 1) * 68 + rp] = hh; sv[VLO + (d4 * 4 + 1) * 68 + rp] = ll;
            split2(va.z, vb.z, hh, ll);
            sv[VHI + (d4 * 4 + 2) * 68 + rp] = hh; sv[VLO + (d4 * 4 + 2) * 68 + rp] = ll;
            split2(va.w, vb.w, hh, ll);
            sv[VHI + (d4 * 4 + 3) * 68 + rp] = hh; sv[VLO + (d4 * 4 + 3) * 68 + rp] = ll;
        }
        __syncthreads();

        float s[16][4];
#pragma unroll
        for (int nt = 0; nt < 16; nt++)
#pragma unroll
            for (int r = 0; r < 4; r++) s[nt][r] = 0.f;

#pragma unroll
        for (int ntp = 0; ntp < 8; ntp++) {
            if (ntp * 2 < ntLo || ntp * 2 > ntHi) continue;
#pragma unroll
            for (int ks = 0; ks < 4; ks++) {
                unsigned bh4[4], bl4[4];
                uint32_t base = sbase + (ntp * 16) * 144 + bRow36 + ks * 32 + bColH;
                ldsm_x4(bh4, base + KHI * 4);
                ldsm_x4(bl4, base + KLO * 4);
                mmabf(s[ntp * 2], aqh[ks], bh4);
                mmabf(s[ntp * 2], aql[ks], bh4);
                mmabf(s[ntp * 2], aqh[ks], bl4);
                mmabf(s[ntp * 2 + 1], aqh[ks], bh4 + 2);
                mmabf(s[ntp * 2 + 1], aql[ks], bh4 + 2);
                mmabf(s[ntp * 2 + 1], aqh[ks], bl4 + 2);
            }
        }

#pragma unroll
        for (int half = 0; half < 2; half++) {
            const int rowg = q0 + qr + half * 8;
            float mx = -1e30f;
#pragma unroll
            for (int nt = 0; nt < 16; nt++) {
                if (nt < ntLo || nt > ntHi) continue;
#pragma unroll
                for (int cc = 0; cc < 2; cc++) {
                    int colg = j0 + nt * 8 + t4 * 2 + cc;
                    bool valid = (colg >= rowg - 127) && (colg <= rowg + 128);
                    float v = valid ? s[nt][half * 2 + cc] * SCALE : -1e30f;
                    s[nt][half * 2 + cc] = v;
                    mx = fmaxf(mx, v);
                }
            }
            mx = fmaxf(mx, __shfl_xor_sync(0xffffffffu, mx, 1));
            mx = fmaxf(mx, __shfl_xor_sync(0xffffffffu, mx, 2));
            float mnew = fmaxf(m_i[half], mx);
            float alpha = __expf(m_i[half] - mnew);
            float sum = 0.f;
#pragma unroll
            for (int nt = 0; nt < 16; nt++) {
                if (nt < ntLo || nt > ntHi) continue;
#pragma unroll
                for (int cc = 0; cc < 2; cc++) {
                    float v = s[nt][half * 2 + cc];
                    float p = (v > -1e29f) ? __expf(v - mnew) : 0.f;
                    sum += p;
                    s[nt][half * 2 + cc] = p;
                }
            }
            sum += __shfl_xor_sync(0xffffffffu, sum, 1);
            sum += __shfl_xor_sync(0xffffffffu, sum, 2);
            l_i[half] = l_i[half] * alpha + sum;
            m_i[half] = mnew;
#pragma unroll
            for (int nt = 0; nt < 8; nt++) {
                o[nt][half * 2] *= alpha;
                o[nt][half * 2 + 1] *= alpha;
            }
            const int rloc = qr + half * 8;
#pragma unroll
            for (int nt = 0; nt < 16; nt++) {
                if (nt < ntLo || nt > ntHi) continue;
                unsigned hh, ll;
                split2(s[nt][half * 2], s[nt][half * 2 + 1], hh, ll);
                sv[PHI + rloc * 68 + nt * 4 + t4] = hh;
                sv[PLO + rloc * 68 + nt * 4 + t4] = ll;
            }
        }
        __syncwarp();

#pragma unroll
        for (int ksp = 0; ksp < 8; ksp++) {
            if (ksp < kspLo || ksp > kspHi) continue;
            unsigned aph[4], apl[4];
            uint32_t pbase = sbase + (wid * 16) * 272 + aRow68 + ksp * 32 + aColH;
            ldsm_x4(aph, pbase + PHI * 4);
            ldsm_x4(apl, pbase + PLO * 4);
#pragma unroll
            for (int ntp = 0; ntp < 4; ntp++) {
                unsigned bh4[4], bl4[4];
                uint32_t vbase = sbase + (ntp * 16) * 272 + bRow68 + ksp * 32 + bColH;
                ldsm_x4(bh4, vbase + VHI * 4);
                ldsm_x4(bl4, vbase + VLO * 4);
                mmabf(o[ntp * 2], aph, bh4);
                mmabf(o[ntp * 2], apl, bh4);
                mmabf(o[ntp * 2], aph, bl4);
                mmabf(o[ntp * 2 + 1], aph, bh4 + 2);
                mmabf(o[ntp * 2 + 1], apl, bh4 + 2);
                mmabf(o[ntp * 2 + 1], aph, bl4 + 2);
            }
        }
        __syncthreads();
    }

    // epilogue: normalize + write ctx as bf16 hi/lo planes (token-major)
#pragma unroll
    for (int half = 0; half < 2; half++) {
        const int rowg = q0 + qr + half * 8;
        const float invl = 1.f / l_i[half];
        const size_t ob = ((size_t)n * TT + rowg) * DM + h * HD;
#pragma unroll
        for (int nt = 0; nt < 8; nt++) {
            int d = nt * 8 + t4 * 2;
            float v0 = o[nt][half * 2] * invl;
            float v1 = o[nt][half * 2 + 1] * invl;
            unsigned hh, ll;
            split2(v0, v1, hh, ll);
            ((unsigned*)g_ch)[(ob + d) >> 1] = hh;
            ((unsigned*)g_cl)[(ob + d) >> 1] = ll;
        }
    }
}

// ---------------------------------------------------------------------------
extern "C" void kernel_launch(void* const* d_in, const int* in_sizes, int n_in,
                              void* d_out, int out_size) {
    const float* x    = (const float*)d_in[0];   // [4,2048,512]
    const float* wqkv = (const float*)d_in[1];   // [1536,512]
    const float* outw = (const float*)d_in[2];   // [512,512]
    const float* outb = (const float*)d_in[3];   // [512]
    float* out = (float*)d_out;

    const int gemm_smem = 2 * GBUF * sizeof(unsigned);            // 81920
    const int att_smem = (PLO + 128 * 68) * sizeof(unsigned);     // 141312

    cudaFuncSetAttribute(gemm_bf<true>, cudaFuncAttributeMaxDynamicSharedMemorySize, gemm_smem);
    cudaFuncSetAttribute(gemm_bf<false>, cudaFuncAttributeMaxDynamicSharedMemorySize, gemm_smem);
    cudaFuncSetAttribute(attn_kernel, cudaFuncAttributeMaxDynamicSharedMemorySize, att_smem);

    __nv_bfloat16 *xh, *xl, *wh, *wl, *owh, *owl;
    cudaGetSymbolAddress((void**)&xh, g_xh);
    cudaGetSymbolAddress((void**)&xl, g_xl);
    cudaGetSymbolAddress((void**)&wh, g_wh);
    cudaGetSymbolAddress((void**)&wl, g_wl);
    cudaGetSymbolAddress((void**)&owh, g_owh);
    cudaGetSymbolAddress((void**)&owl, g_owl);

    rope_table_kernel<<<(TT * 32 + 255) / 256, 256>>>();
    conv_kernel<<<(8192 * 512 / 4 + 255) / 256, 256>>>(x, xh, xl, 8192 * 512 / 4);
    conv_kernel<<<(1536 * 512 / 4 + 255) / 256, 256>>>(wqkv, wh, wl, 1536 * 512 / 4);
    conv_kernel<<<(512 * 512 / 4 + 255) / 256, 256>>>(outw, owh, owl, 512 * 512 / 4);

    gemm_bf<true><<<dim3(1536 / 128, 8192 / 128), 256, gemm_smem>>>(nullptr, nullptr);
    attn_kernel<<<dim3(TT / 128, NH, NB), 256, att_smem>>>();
    gemm_bf<false><<<dim3(512 / 128, 8192 / 128), 256, gemm_smem>>>(outb, out);
}

// round 8
// speedup vs baseline: 1.1555x; 1.1555x over previous
#include <cuda_runtime.h>
#include <math.h>
#include <cstdint>

#define NB 4
#define TT 2048
#define DM 512
#define NH 8
#define HD 64
#define SCALE 0.125f

// Scratch (no allocation allowed)
__device__ float g_q[NB * NH * TT * HD];
__device__ float g_k[NB * NH * TT * HD];
__device__ float g_v[NB * NH * TT * HD];
__device__ float g_ctx[NB * TT * DM];
__device__ float g_rc[TT * 32];
__device__ float g_rs[TT * 32];

// pack two floats -> bf16x2 (e0 in low half), rne
__device__ __forceinline__ unsigned pack2(float e0, float e1) {
    unsigned r;
    asm("cvt.rn.bf16x2.f32 %0, %1, %2;" : "=r"(r) : "f"(e1), "f"(e0));
    return r;
}
__device__ __forceinline__ void split2(float f0, float f1, unsigned& hi, unsigned& lo) {
    unsigned h = pack2(f0, f1);
    float h0 = __uint_as_float(h << 16);
    float h1 = __uint_as_float(h & 0xFFFF0000u);
    lo = pack2(f0 - h0, f1 - h1);
    hi = h;
}
__device__ __forceinline__ void mmabf(float* c, const unsigned* a, const unsigned* b) {
    asm volatile(
        "mma.sync.aligned.m16n8k16.row.col.f32.bf16.bf16.f32 "
        "{%0,%1,%2,%3},{%4,%5,%6,%7},{%8,%9},{%0,%1,%2,%3};"
        : "+f"(c[0]), "+f"(c[1]), "+f"(c[2]), "+f"(c[3])
        : "r"(a[0]), "r"(a[1]), "r"(a[2]), "r"(a[3]), "r"(b[0]), "r"(b[1]));
}
__device__ __forceinline__ uint32_t smem_u32(const void* p) {
    uint32_t a;
    asm("{ .reg .u64 t; cvta.to.shared.u64 t, %1; cvt.u32.u64 %0, t; }" : "=r"(a) : "l"(p));
    return a;
}
__device__ __forceinline__ void ldsm_x4(unsigned* r, uint32_t addr) {
    asm volatile("ldmatrix.sync.aligned.m8n8.x4.shared.b16 {%0,%1,%2,%3}, [%4];"
                 : "=r"(r[0]), "=r"(r[1]), "=r"(r[2]), "=r"(r[3]) : "r"(addr));
}

// ---------------------------------------------------------------------------
// BF16x3 GEMM with ldmatrix fragment loads (R6 known-good).
// Block 128m x 64e, 8 warps (4m x 2e), warp tile 32x32, K-chunk 32, dbl-buffered.
// ---------------------------------------------------------------------------
#define GAH 0
#define GAL 2560
#define GWH 5120
#define GWL 6400
#define GBUF 7680

template <bool QKV>
__global__ void __launch_bounds__(256) gemm_bf(const float* __restrict__ A,
                                               const float* __restrict__ W,
                                               const float* __restrict__ bias,
                                               float* __restrict__ out) {
    extern __shared__ unsigned gsm[];
    const uint32_t sbase = smem_u32(gsm);

    const int e0 = blockIdx.x * 64;
    const int m0 = blockIdx.y * 128;
    const int tid = threadIdx.x;
    const int wid = tid >> 5, lane = tid & 31;
    const int wm = wid >> 1, wn = wid & 1;
    const int g = lane >> 2, t4 = lane & 3;

    const float* Ap = QKV ? A : (const float*)g_ctx;

    float acc[2][4][4];
#pragma unroll
    for (int mt = 0; mt < 2; mt++)
#pragma unroll
        for (int nt = 0; nt < 4; nt++)
#pragma unroll
            for (int r = 0; r < 4; r++) acc[mt][nt][r] = 0.f;

    float4 av[4], wv[2];

#define LDG_CHUNK(KC)                                                              \
    do {                                                                           \
        _Pragma("unroll") for (int i = 0; i < 4; i++) {                            \
            int idx = tid + i * 256;                                               \
            int r = idx >> 3, k4 = idx & 7;                                        \
            av[i] = *(const float4*)(Ap + (size_t)(m0 + r) * 512 + (KC) + k4 * 4); \
        }                                                                          \
        _Pragma("unroll") for (int i = 0; i < 2; i++) {                            \
            int idx = tid + i * 256;                                               \
            int r = idx >> 3, k4 = idx & 7;                                        \
            wv[i] = *(const float4*)(W + (size_t)(e0 + r) * 512 + (KC) + k4 * 4);  \
        }                                                                          \
    } while (0)

#define STS_CHUNK(BUF)                                                    \
    do {                                                                  \
        unsigned* b_ = (BUF);                                             \
        _Pragma("unroll") for (int i = 0; i < 4; i++) {                   \
            int idx = tid + i * 256;                                      \
            int r = idx >> 3, k4 = idx & 7;                               \
            unsigned h0, l0, h1, l1;                                      \
            split2(av[i].x, av[i].y, h0, l0);                             \
            split2(av[i].z, av[i].w, h1, l1);                             \
            *(uint2*)&b_[GAH + r * 20 + k4 * 2] = make_uint2(h0, h1);     \
            *(uint2*)&b_[GAL + r * 20 + k4 * 2] = make_uint2(l0, l1);     \
        }                                                                 \
        _Pragma("unroll") for (int i = 0; i < 2; i++) {                   \
            int idx = tid + i * 256;                                      \
            int r = idx >> 3, k4 = idx & 7;                               \
            unsigned h0, l0, h1, l1;                                      \
            split2(wv[i].x, wv[i].y, h0, l0);                             \
            split2(wv[i].z, wv[i].w, h1, l1);                             \
            *(uint2*)&b_[GWH + r * 20 + k4 * 2] = make_uint2(h0, h1);     \
            *(uint2*)&b_[GWL + r * 20 + k4 * 2] = make_uint2(l0, l1);     \
        }                                                                 \
    } while (0)

    LDG_CHUNK(0);
    STS_CHUNK(gsm);
    __syncthreads();

    const uint32_t aRowOff = (uint32_t)(lane & 15) * 80;
    const uint32_t aColOff = (uint32_t)(lane >> 4) * 16;
    const uint32_t bRowOff = (uint32_t)((lane & 7) + ((lane >> 4) << 3)) * 80;
    const uint32_t bColOff = (uint32_t)((lane >> 3) & 1) * 16;

    int cur = 0;
    for (int kc = 0; kc < 512; kc += 32) {
        if (kc + 32 < 512) LDG_CHUNK(kc + 32);
        const uint32_t bb = sbase + cur * (GBUF * 4);
#pragma unroll
        for (int ks = 0; ks < 2; ks++) {
            unsigned ah[2][4], al[2][4], bh[2][4], bl[2][4];
            const uint32_t kOff = ks * 32;
#pragma unroll
            for (int mt = 0; mt < 2; mt++) {
                uint32_t base = bb + (wm * 32 + mt * 16) * 80 + aRowOff + kOff + aColOff;
                ldsm_x4(ah[mt], base + GAH * 4);
                ldsm_x4(al[mt], base + GAL * 4);
            }
#pragma unroll
            for (int ntp = 0; ntp < 2; ntp++) {
                uint32_t base = bb + (wn * 32 + ntp * 16) * 80 + bRowOff + kOff + bColOff;
                ldsm_x4(bh[ntp], base + GWH * 4);
                ldsm_x4(bl[ntp], base + GWL * 4);
            }
#pragma unroll
            for (int mt = 0; mt < 2; mt++)
#pragma unroll
                for (int nt = 0; nt < 4; nt++) {
                    const unsigned* BH = &bh[nt >> 1][(nt & 1) * 2];
                    const unsigned* BL = &bl[nt >> 1][(nt & 1) * 2];
                    mmabf(acc[mt][nt], ah[mt], BH);
                    mmabf(acc[mt][nt], al[mt], BH);
                    mmabf(acc[mt][nt], ah[mt], BL);
                }
        }
        if (kc + 32 < 512) STS_CHUNK(gsm + (cur ^ 1) * GBUF);
        __syncthreads();
        cur ^= 1;
    }

    if (QKV) {
        const int sec = e0 >> 9;
        const int h = (e0 >> 6) & 7;
        float* buf = (sec == 0) ? g_q : (sec == 1) ? g_k : g_v;
#pragma unroll
        for (int mt = 0; mt < 2; mt++)
#pragma unroll
            for (int half = 0; half < 2; half++) {
                int m = m0 + wm * 32 + mt * 16 + g + half * 8;
                int nbt = m >> 11, tt = m & 2047;
                size_t base = (((size_t)(nbt * NH + h)) * TT + tt) * HD;
#pragma unroll
                for (int nt = 0; nt < 4; nt++) {
                    int d = wn * 32 + nt * 8 + t4 * 2;
                    *(float2*)(buf + base + d) =
                        make_float2(acc[mt][nt][half * 2], acc[mt][nt][half * 2 + 1]);
                }
            }
    } else {
#pragma unroll
        for (int mt = 0; mt < 2; mt++)
#pragma unroll
            for (int half = 0; half < 2; half++) {
                int m = m0 + wm * 32 + mt * 16 + g + half * 8;
#pragma unroll
                for (int nt = 0; nt < 4; nt++) {
                    int e = e0 + wn * 32 + nt * 8 + t4 * 2;
                    float2 bv = *(const float2*)(bias + e);
                    *(float2*)(out + (size_t)m * 512 + e) =
                        make_float2(acc[mt][nt][half * 2] + bv.x,
                                    acc[mt][nt][half * 2 + 1] + bv.y);
                }
            }
    }
}

// ---------------------------------------------------------------------------
// RoPE trig table
// ---------------------------------------------------------------------------
__global__ void __launch_bounds__(256) rope_table_kernel() {
    int idx = blockIdx.x * 256 + threadIdx.x;
    if (idx >= TT * 32) return;
    int t = idx >> 5, lane = idx & 31;
    double inv_freq = pow(10000.0, -((double)(2 * lane) / 64.0));
    float ang = (float)t * (float)inv_freq;
    g_rc[idx] = (float)cos((double)ang);
    g_rs[idx] = (float)sin((double)ang);
}

// ---------------------------------------------------------------------------
// Sliding-window attention, bf16x3, ldmatrix K/V/Q, RoPE fused in staging.
// P kept in registers (C-frag -> A-frag repack). smem: K,V only (71.7KB).
// ---------------------------------------------------------------------------
#define KHI 0
#define KLO 4608
#define VHI 9216
#define VLO 13568
#define ATT_SMEM_U32 17920

__global__ void __launch_bounds__(256) attn_kernel() {
    extern __shared__ unsigned sv[];
    const uint32_t sbase = smem_u32(sv);

    const int qt = blockIdx.x;
    const int h = blockIdx.y;
    const int n = blockIdx.z;
    const int q0 = qt * 128;
    const int tid = threadIdx.x;
    const int wid = tid >> 5, lane = tid & 31;
    const int g = lane >> 2, t4 = lane & 3;
    const int qr = wid * 16 + g;

    const size_t hb = ((size_t)(n * NH + h)) * TT * HD;
    const float* qg = g_q + hb;
    const float* kg = g_k + hb;
    const float* vg = g_v + hb;

    const uint32_t aRow36 = (uint32_t)(lane & 15) * 144;
    const uint32_t aColH = (uint32_t)(lane >> 4) * 16;
    const uint32_t bRow36 = (uint32_t)((lane & 7) + ((lane >> 4) << 3)) * 144;
    const uint32_t bRow68 = (uint32_t)((lane & 7) + ((lane >> 4) << 3)) * 272;
    const uint32_t bColH = (uint32_t)((lane >> 3) & 1) * 16;

    // ---- stage Q with fused RoPE into the K region (freed before the loop) ----
#pragma unroll
    for (int i = 0; i < 4; i++) {
        int idx = tid + i * 256;
        int r = idx >> 3, d4 = idx & 7;
        const float* row = qg + (size_t)(q0 + r) * HD;
        float4 a = *(const float4*)(row + d4 * 4);
        float4 b = *(const float4*)(row + d4 * 4 + 32);
        const float4 cv = *(const float4*)(g_rc + (size_t)(q0 + r) * 32 + d4 * 4);
        const float4 sn = *(const float4*)(g_rs + (size_t)(q0 + r) * 32 + d4 * 4);
        float4 lo = make_float4(a.x * cv.x - b.x * sn.x, a.y * cv.y - b.y * sn.y,
                                a.z * cv.z - b.z * sn.z, a.w * cv.w - b.w * sn.w);
        float4 hi = make_float4(b.x * cv.x + a.x * sn.x, b.y * cv.y + a.y * sn.y,
                                b.z * cv.z + a.z * sn.z, b.w * cv.w + a.w * sn.w);
        unsigned h0, l0, h1, l1;
        split2(lo.x, lo.y, h0, l0);
        split2(lo.z, lo.w, h1, l1);
        *(uint2*)&sv[KHI + r * 36 + d4 * 2] = make_uint2(h0, h1);
        *(uint2*)&sv[KLO + r * 36 + d4 * 2] = make_uint2(l0, l1);
        split2(hi.x, hi.y, h0, l0);
        split2(hi.z, hi.w, h1, l1);
        *(uint2*)&sv[KHI + r * 36 + (d4 + 8) * 2] = make_uint2(h0, h1);
        *(uint2*)&sv[KLO + r * 36 + (d4 + 8) * 2] = make_uint2(l0, l1);
    }
    __syncthreads();

    unsigned aqh[4][4], aql[4][4];
#pragma unroll
    for (int ks = 0; ks < 4; ks++) {
        uint32_t base = sbase + (wid * 16) * 144 + aRow36 + ks * 32 + aColH;
        ldsm_x4(aqh[ks], base + KHI * 4);
        ldsm_x4(aql[ks], base + KLO * 4);
    }
    __syncthreads();

    float m_i[2] = {-1e30f, -1e30f};
    float l_i[2] = {0.f, 0.f};
    float o[8][4];
#pragma unroll
    for (int nt = 0; nt < 8; nt++)
#pragma unroll
        for (int r = 0; r < 4; r++) o[nt][r] = 0.f;

    int c0 = qt - 1; if (c0 < 0) c0 = 0;
    int c1 = qt + 1; if (c1 > 15) c1 = 15;

    for (int c = c0; c <= c1; c++) {
        const int j0 = c * 128;

        const int rowlo = q0 + wid * 16;
        int ntLo = (rowlo - 127 - j0) >> 3;
        if (ntLo < 0) ntLo = 0;
        ntLo &= ~1;
        int ntHi = (rowlo + 15 + 128 - j0) >> 3;
        if (ntHi > 15) ntHi = 15;
        ntHi |= 1;
        const int kspLo = ntLo >> 1, kspHi = ntHi >> 1;

        // ---- stage K with fused RoPE ----
#pragma unroll
        for (int i = 0; i < 4; i++) {
            int idx = tid + i * 256;
            int r = idx >> 3, d4 = idx & 7;
            const float* row = kg + (size_t)(j0 + r) * HD;
            float4 a = *(const float4*)(row + d4 * 4);
            float4 b = *(const float4*)(row + d4 * 4 + 32);
            const float4 cv = *(const float4*)(g_rc + (size_t)(j0 + r) * 32 + d4 * 4);
            const float4 sn = *(const float4*)(g_rs + (size_t)(j0 + r) * 32 + d4 * 4);
            float4 lo = make_float4(a.x * cv.x - b.x * sn.x, a.y * cv.y - b.y * sn.y,
                                    a.z * cv.z - b.z * sn.z, a.w * cv.w - b.w * sn.w);
            float4 hi = make_float4(b.x * cv.x + a.x * sn.x, b.y * cv.y + a.y * sn.y,
                                    b.z * cv.z + a.z * sn.z, b.w * cv.w + a.w * sn.w);
            unsigned h0, l0, h1, l1;
            split2(lo.x, lo.y, h0, l0);
            split2(lo.z, lo.w, h1, l1);
            *(uint2*)&sv[KHI + r * 36 + d4 * 2] = make_uint2(h0, h1);
            *(uint2*)&sv[KLO + r * 36 + d4 * 2] = make_uint2(l0, l1);
            split2(hi.x, hi.y, h0, l0);
            split2(hi.z, hi.w, h1, l1);
            *(uint2*)&sv[KHI + r * 36 + (d4 + 8) * 2] = make_uint2(h0, h1);
            *(uint2*)&sv[KLO + r * 36 + (d4 + 8) * 2] = make_uint2(l0, l1);
        }
        // ---- stage V transposed: Vt[dim][keypair], stride 68 ----
#pragma unroll
        for (int i = 0; i < 4; i++) {
            int idx = tid + i * 256;
            int rp = idx >> 4, d4 = idx & 15;
            float4 va = *(const float4*)(vg + (size_t)(j0 + 2 * rp) * HD + d4 * 4);
            float4 vb = *(const float4*)(vg + (size_t)(j0 + 2 * rp + 1) * HD + d4 * 4);
            unsigned hh, ll;
            split2(va.x, vb.x, hh, ll);
            sv[VHI + (d4 * 4 + 0) * 68 + rp] = hh; sv[VLO + (d4 * 4 + 0) * 68 + rp] = ll;
            split2(va.y, vb.y, hh, ll);
            sv[VHI + (d4 * 4 + 1) * 68 + rp] = hh; sv[VLO + (d4 * 4 + 1) * 68 + rp] = ll;
            split2(va.z, vb.z, hh, ll);
            sv[VHI + (d4 * 4 + 2) * 68 + rp] = hh; sv[VLO + (d4 * 4 + 2) * 68 + rp] = ll;
            split2(va.w, vb.w, hh, ll);
            sv[VHI + (d4 * 4 + 3) * 68 + rp] = hh; sv[VLO + (d4 * 4 + 3) * 68 + rp] = ll;
        }
        __syncthreads();

        // ---- S = Q . K^T (live n-tile pairs, ldmatrix x4) ----
        float s[16][4];
#pragma unroll
        for (int nt = 0; nt < 16; nt++)
#pragma unroll
            for (int r = 0; r < 4; r++) s[nt][r] = 0.f;

#pragma unroll
        for (int ntp = 0; ntp < 8; ntp++) {
            if (ntp * 2 < ntLo || ntp * 2 > ntHi) continue;
#pragma unroll
            for (int ks = 0; ks < 4; ks++) {
                unsigned bh4[4], bl4[4];
                uint32_t base = sbase + (ntp * 16) * 144 + bRow36 + ks * 32 + bColH;
                ldsm_x4(bh4, base + KHI * 4);
                ldsm_x4(bl4, base + KLO * 4);
                mmabf(s[ntp * 2], aqh[ks], bh4);
                mmabf(s[ntp * 2], aql[ks], bh4);
                mmabf(s[ntp * 2], aqh[ks], bl4);
                mmabf(s[ntp * 2 + 1], aqh[ks], bh4 + 2);
                mmabf(s[ntp * 2 + 1], aql[ks], bh4 + 2);
                mmabf(s[ntp * 2 + 1], aqh[ks], bl4 + 2);
            }
        }

        // ---- mask + online softmax (P stays in s[] registers) ----
#pragma unroll
        for (int half = 0; half < 2; half++) {
            const int rowg = q0 + qr + half * 8;
            float mx = -1e30f;
#pragma unroll
            for (int nt = 0; nt < 16; nt++) {
                if (nt < ntLo || nt > ntHi) continue;
#pragma unroll
                for (int cc = 0; cc < 2; cc++) {
                    int colg = j0 + nt * 8 + t4 * 2 + cc;
                    bool valid = (colg >= rowg - 127) && (colg <= rowg + 128);
                    float v = valid ? s[nt][half * 2 + cc] * SCALE : -1e30f;
                    s[nt][half * 2 + cc] = v;
                    mx = fmaxf(mx, v);
                }
            }
            mx = fmaxf(mx, __shfl_xor_sync(0xffffffffu, mx, 1));
            mx = fmaxf(mx, __shfl_xor_sync(0xffffffffu, mx, 2));
            float mnew = fmaxf(m_i[half], mx);
            float alpha = __expf(m_i[half] - mnew);
            float sum = 0.f;
#pragma unroll
            for (int nt = 0; nt < 16; nt++) {
                if (nt < ntLo || nt > ntHi) continue;
#pragma unroll
                for (int cc = 0; cc < 2; cc++) {
                    float v = s[nt][half * 2 + cc];
                    float p = (v > -1e29f) ? __expf(v - mnew) : 0.f;
                    sum += p;
                    s[nt][half * 2 + cc] = p;
                }
            }
            sum += __shfl_xor_sync(0xffffffffu, sum, 1);
            sum += __shfl_xor_sync(0xffffffffu, sum, 2);
            l_i[half] = l_i[half] * alpha + sum;
            m_i[half] = mnew;
#pragma unroll
            for (int nt = 0; nt < 8; nt++) {
                o[nt][half * 2] *= alpha;
                o[nt][half * 2 + 1] *= alpha;
            }
        }

        // ---- O += P . V  (P repacked from score C-frags in registers) ----
#pragma unroll
        for (int ksp = 0; ksp < 8; ksp++) {
            if (ksp < kspLo || ksp > kspHi) continue;
            unsigned aph[4], apl[4];
            split2(s[2 * ksp][0], s[2 * ksp][1], aph[0], apl[0]);
            split2(s[2 * ksp][2], s[2 * ksp][3], aph[1], apl[1]);
            split2(s[2 * ksp + 1][0], s[2 * ksp + 1][1], aph[2], apl[2]);
            split2(s[2 * ksp + 1][2], s[2 * ksp + 1][3], aph[3], apl[3]);
#pragma unroll
            for (int ntp = 0; ntp < 4; ntp++) {
                unsigned bh4[4], bl4[4];
                uint32_t vbase = sbase + (ntp * 16) * 272 + bRow68 + ksp * 32 + bColH;
                ldsm_x4(bh4, vbase + VHI * 4);
                ldsm_x4(bl4, vbase + VLO * 4);
                mmabf(o[ntp * 2], aph, bh4);
                mmabf(o[ntp * 2], apl, bh4);
                mmabf(o[ntp * 2], aph, bl4);
                mmabf(o[ntp * 2 + 1], aph, bh4 + 2);
                mmabf(o[ntp * 2 + 1], apl, bh4 + 2);
                mmabf(o[ntp * 2 + 1], aph, bl4 + 2);
            }
        }
        __syncthreads();
    }

    // ---- epilogue ----
#pragma unroll
    for (int half = 0; half < 2; half++) {
        const int rowg = q0 + qr + half * 8;
        const float invl = 1.f / l_i[half];
        const size_t ob = ((size_t)n * TT + rowg) * DM + h * HD;
#pragma unroll
        for (int nt = 0; nt < 8; nt++) {
            int d = nt * 8 + t4 * 2;
            *(float2*)(g_ctx + ob + d) =
                make_float2(o[nt][half * 2] * invl, o[nt][half * 2 + 1] * invl);
        }
    }
}

// ---------------------------------------------------------------------------
extern "C" void kernel_launch(void* const* d_in, const int* in_sizes, int n_in,
                              void* d_out, int out_size) {
    const float* x    = (const float*)d_in[0];   // [4,2048,512]
    const float* wqkv = (const float*)d_in[1];   // [1536,512]
    const float* outw = (const float*)d_in[2];   // [512,512]
    const float* outb = (const float*)d_in[3];   // [512]
    float* out = (float*)d_out;

    const int gemm_smem = 2 * GBUF * sizeof(unsigned);        // 61440
    const int att_smem = ATT_SMEM_U32 * sizeof(unsigned);     // 71680

    cudaFuncSetAttribute(gemm_bf<true>, cudaFuncAttributeMaxDynamicSharedMemorySize, gemm_smem);
    cudaFuncSetAttribute(gemm_bf<false>, cudaFuncAttributeMaxDynamicSharedMemorySize, gemm_smem);
    cudaFuncSetAttribute(attn_kernel, cudaFuncAttributeMaxDynamicSharedMemorySize, att_smem);

    rope_table_kernel<<<(TT * 32 + 255) / 256, 256>>>();
    gemm_bf<true><<<dim3(1536 / 64, 8192 / 128), 256, gemm_smem>>>(x, wqkv, nullptr, nullptr);
    attn_kernel<<<dim3(TT / 128, NH, NB), 256, att_smem>>>();
    gemm_bf<false><<<dim3(512 / 64, 8192 / 128), 256, gemm_smem>>>(nullptr, outw, outb, out);
}